// round 17
// baseline (speedup 1.0000x reference)
#include <cuda_runtime.h>
#include <cuda_fp16.h>

#define NMAX 100000
#define HDIM 64
#define SLOTS 128     // max degree safety: Poisson(32) max over 100k nodes ~58

// ---- device scratch (no allocations allowed), 16B-aligned ----
__device__ __align__(16) int     d_cnt [NMAX];
__device__ __align__(16) int     d_adj [(size_t)NMAX * SLOTS];  // padded adjacency
__device__ __align__(16) float   d_dinv[NMAX];
// +1 row: dummy zero node (index NMAX) used for tail padding
__device__ __align__(16) __half2 d_gh[(size_t)(NMAX + 1) * (HDIM / 2)];
__device__ __align__(16) float   d_S [(size_t)NMAX * HDIM];     // propagate result (fp32)

#define BUF_EXT 0
#define BUF_S   1

__device__ __forceinline__ __half2 u2h2(unsigned int u) {
    __half2 h; *(unsigned int*)&h = u; return h;
}

// ---- tensor-core helpers (mma.sync m16n8k16 f16 -> f32) ----
__device__ __forceinline__ unsigned smem_u32p(const void* p) {
    return (unsigned)__cvta_generic_to_shared(p);
}
__device__ __forceinline__ void ldm_x4(unsigned& r0, unsigned& r1,
                                       unsigned& r2, unsigned& r3, unsigned addr) {
    asm volatile("ldmatrix.sync.aligned.m8n8.x4.shared.b16 {%0,%1,%2,%3}, [%4];"
                 : "=r"(r0), "=r"(r1), "=r"(r2), "=r"(r3) : "r"(addr));
}
__device__ __forceinline__ void ldm_x4_t(unsigned& r0, unsigned& r1,
                                         unsigned& r2, unsigned& r3, unsigned addr) {
    asm volatile("ldmatrix.sync.aligned.m8n8.x4.trans.shared.b16 {%0,%1,%2,%3}, [%4];"
                 : "=r"(r0), "=r"(r1), "=r"(r2), "=r"(r3) : "r"(addr));
}
__device__ __forceinline__ void mma16816(float c[4],
                                         unsigned a0, unsigned a1, unsigned a2, unsigned a3,
                                         unsigned b0, unsigned b1) {
    asm volatile("mma.sync.aligned.m16n8k16.row.col.f32.f16.f16.f32 "
                 "{%0,%1,%2,%3}, {%4,%5,%6,%7}, {%8,%9}, {%0,%1,%2,%3};"
                 : "+f"(c[0]), "+f"(c[1]), "+f"(c[2]), "+f"(c[3])
                 : "r"(a0), "r"(a1), "r"(a2), "r"(a3), "r"(b0), "r"(b1));
}

template<int PA, int PW>
__device__ __forceinline__ void mma_k16(float acc[8][4], const __half* A, int mbase, int ka,
                                        const __half* Wt, int kw, int lane) {
    unsigned a0, a1, a2, a3;
    int arow = mbase + (lane & 15);
    int acol = ka + ((lane >> 4) << 3);
    ldm_x4(a0, a1, a2, a3, smem_u32p(&A[arow * PA + acol]));
    int q = lane >> 3;
    int lr = lane & 7;
    int krow = kw + lr + ((q & 1) << 3);
#pragma unroll
    for (int nb2 = 0; nb2 < 4; nb2++) {
        int ncol = (nb2 << 4) + ((q >> 1) << 3);
        unsigned b0, b1, b2, b3;
        ldm_x4_t(b0, b1, b2, b3, smem_u32p(&Wt[krow * PW + ncol]));
        mma16816(acc[2 * nb2],     a0, a1, a2, a3, b0, b1);
        mma16816(acc[2 * nb2 + 1], a0, a1, a2, a3, b2, b3);
    }
}

// ------------------------------------------------------------------
// adjacency build (edge_index is int32: JAX x64 disabled)
// ------------------------------------------------------------------
__global__ void zero_cnt_kernel(int n) {
    int i = blockIdx.x * blockDim.x + threadIdx.x;
    if (i < n) d_cnt[i] = 0;
    if (i < 32)
        ((unsigned int*)&d_gh[(size_t)NMAX * 32])[i] = 0u;
}

__global__ void fill_adj_kernel(const int* __restrict__ e0,
                                const int* __restrict__ e1, int E) {
    int e = blockIdx.x * blockDim.x + threadIdx.x;
    if (e >= E) return;
    int u = __ldg(&e0[e]);
    int v = __ldg(&e1[e]);
    int pu = atomicAdd(&d_cnt[u], 1);
    if (pu < SLOTS) d_adj[(size_t)u * SLOTS + pu] = v;
    int pv = atomicAdd(&d_cnt[v], 1);
    if (pv < SLOTS) d_adj[(size_t)v * SLOTS + pv] = u;
}

// ------------------------------------------------------------------
// propagate (gather-only, double-buffered): S[i] = sum_{j in adj[i]} g[j]
// warp per node; half-warp w = neighbor substream; lane covers 4 cols.
// Data group j+1 and idx group j+2 are in flight while group j accumulates.
// ------------------------------------------------------------------
__global__ __launch_bounds__(256)
void gather_kernel(int nn) {
    int node = blockIdx.x * 8 + (threadIdx.x >> 5);
    int lane = threadIdx.x & 31;
    if (node >= nn) return;
    int w = lane >> 4;
    int c = lane & 15;
    int cnt = min(d_cnt[node], SLOTS);
    int grp = min((cnt + 7) & ~7, SLOTS) >> 3;   // number of 8-neighbor groups
    const int* adj = &d_adj[(size_t)node * SLOTS];
    const uint2* gh2 = (const uint2*)d_gh;       // node row = 16 uint2

    float4 facc = make_float4(0.f, 0.f, 0.f, 0.f);
    if (grp == 0) {
        if (w == 0) ((float4*)d_S)[(size_t)node * 16 + c] = facc;
        return;
    }

    // prologue: idx g0, data g0, idx g1
    int4 nbB = __ldg((const int4*)&adj[4 * w]);
    uint2 c0 = __ldg(&gh2[(size_t)nbB.x * 16 + c]);
    uint2 c1 = __ldg(&gh2[(size_t)nbB.y * 16 + c]);
    uint2 c2 = __ldg(&gh2[(size_t)nbB.z * 16 + c]);
    uint2 c3 = __ldg(&gh2[(size_t)nbB.w * 16 + c]);
    if (grp > 1) nbB = __ldg((const int4*)&adj[8 + 4 * w]);
    int4 nbA = nbB;

    for (int j = 0; j < grp; j++) {
        uint2 n0, n1, n2, n3;
        if (j + 1 < grp) {                      // data prefetch for group j+1
            n0 = __ldg(&gh2[(size_t)nbB.x * 16 + c]);
            n1 = __ldg(&gh2[(size_t)nbB.y * 16 + c]);
            n2 = __ldg(&gh2[(size_t)nbB.z * 16 + c]);
            n3 = __ldg(&gh2[(size_t)nbB.w * 16 + c]);
        }
        if (j + 2 < grp)                        // idx prefetch for group j+2
            nbA = __ldg((const int4*)&adj[8 * (j + 2) + 4 * w]);
        // accumulate group j
        __half2 h0 = __hadd2(__hadd2(u2h2(c0.x), u2h2(c1.x)),
                             __hadd2(u2h2(c2.x), u2h2(c3.x)));
        __half2 h1 = __hadd2(__hadd2(u2h2(c0.y), u2h2(c1.y)),
                             __hadd2(u2h2(c2.y), u2h2(c3.y)));
        float2 f0 = __half22float2(h0);
        float2 f1 = __half22float2(h1);
        facc.x += f0.x; facc.y += f0.y; facc.z += f1.x; facc.w += f1.y;
        c0 = n0; c1 = n1; c2 = n2; c3 = n3;
        nbB = nbA;
    }
    facc.x += __shfl_xor_sync(0xffffffffu, facc.x, 16);
    facc.y += __shfl_xor_sync(0xffffffffu, facc.y, 16);
    facc.z += __shfl_xor_sync(0xffffffffu, facc.z, 16);
    facc.w += __shfl_xor_sync(0xffffffffu, facc.w, 16);
    if (w == 0)
        ((float4*)d_S)[(size_t)node * 16 + c] = facc;
}

// ==================================================================
// gemmA (fused, TENSOR-CORE): h = x@W_in+b_in; g = dinv*relu(h@W1+b1) -> d_gh
// epilogue additionally pads adjacency lists (replaces pad_adj kernel).
// ==================================================================
#define AP1 40   // phase-1 A tile pitch (halves)
#define HP1 72   // Hs / Wt / A pitch (halves)

__global__ __launch_bounds__(256, 2)
void gemm_fused_A(const float* __restrict__ x,
                  const float* __restrict__ W_in, const float* __restrict__ b_in,
                  const float* __restrict__ W1,   const float* __restrict__ b1,
                  int nn) {
    __shared__ __align__(16) __half sU1[128 * HP1];
    __shared__ __align__(16) __half sU2[128 * AP1];
    __shared__ float sB[128];

    int tid = threadIdx.x;
    int warp = tid >> 5, lane = tid & 31;
    int m0 = blockIdx.x * 128;
    int mbase = warp * 16;

#pragma unroll
    for (int l = 0; l < 8; l++) {
        int fi = tid + l * 256;
        int k = fi >> 4;
        int n4 = (fi & 15) * 4;
        float4 w4 = __ldg((const float4*)(W_in + (size_t)k * 64 + n4));
        __half2 h0 = __floats2half2_rn(w4.x, w4.y);
        __half2 h1 = __floats2half2_rn(w4.z, w4.w);
        uint2 pk; pk.x = *(unsigned*)&h0; pk.y = *(unsigned*)&h1;
        *(uint2*)&sU1[k * HP1 + n4] = pk;
    }
    if (tid < 64)       sB[tid] = __ldg(b_in + tid);
    else if (tid < 128) sB[tid] = __ldg(b1 + tid - 64);

    float acc[8][4];
#pragma unroll
    for (int i = 0; i < 8; i++)
#pragma unroll
        for (int j = 0; j < 4; j++) acc[i][j] = 0.f;

    float4 xr[4];
#pragma unroll
    for (int l = 0; l < 4; l++) {
        int fi = tid + l * 256;
        int node = fi >> 3, q = fi & 7;
        int gm = m0 + node;
        xr[l] = (gm < nn) ? __ldg((const float4*)(x + (size_t)gm * 128 + 4 * q))
                          : make_float4(0.f, 0.f, 0.f, 0.f);
    }
#pragma unroll
    for (int kc = 0; kc < 128; kc += 32) {
        __syncthreads();
#pragma unroll
        for (int l = 0; l < 4; l++) {
            int fi = tid + l * 256;
            int node = fi >> 3, q = fi & 7;
            __half2 h0 = __floats2half2_rn(xr[l].x, xr[l].y);
            __half2 h1 = __floats2half2_rn(xr[l].z, xr[l].w);
            uint2 pk; pk.x = *(unsigned*)&h0; pk.y = *(unsigned*)&h1;
            *(uint2*)&sU2[node * AP1 + 4 * q] = pk;
        }
        __syncthreads();
        if (kc + 32 < 128) {
#pragma unroll
            for (int l = 0; l < 4; l++) {
                int fi = tid + l * 256;
                int node = fi >> 3, q = fi & 7;
                int gm = m0 + node;
                xr[l] = (gm < nn)
                    ? __ldg((const float4*)(x + (size_t)gm * 128 + kc + 32 + 4 * q))
                    : make_float4(0.f, 0.f, 0.f, 0.f);
            }
        }
        mma_k16<AP1, HP1>(acc, sU2, mbase, 0,  sU1, kc,      lane);
        mma_k16<AP1, HP1>(acc, sU2, mbase, 16, sU1, kc + 16, lane);
    }
    __syncthreads();

    int g = lane >> 2, t = lane & 3;
#pragma unroll
    for (int nb = 0; nb < 8; nb++) {
        int n0 = nb * 8 + 2 * t;
        float bx = sB[n0], by = sB[n0 + 1];
        *(__half2*)&sU1[(mbase + g) * HP1 + n0] =
            __floats2half2_rn(acc[nb][0] + bx, acc[nb][1] + by);
        *(__half2*)&sU1[(mbase + g + 8) * HP1 + n0] =
            __floats2half2_rn(acc[nb][2] + bx, acc[nb][3] + by);
    }
#pragma unroll
    for (int l = 0; l < 4; l++) {
        int fi = tid + l * 256;
        int k = fi >> 4;
        int n4 = (fi & 15) * 4;
        float4 w4 = __ldg((const float4*)(W1 + (size_t)k * 64 + n4));
        __half2 h0 = __floats2half2_rn(w4.x, w4.y);
        __half2 h1 = __floats2half2_rn(w4.z, w4.w);
        uint2 pk; pk.x = *(unsigned*)&h0; pk.y = *(unsigned*)&h1;
        *(uint2*)&sU2[k * HP1 + n4] = pk;
    }
    __syncthreads();

    float acc2[8][4];
#pragma unroll
    for (int i = 0; i < 8; i++)
#pragma unroll
        for (int j = 0; j < 4; j++) acc2[i][j] = 0.f;
#pragma unroll
    for (int k16 = 0; k16 < 64; k16 += 16)
        mma_k16<HP1, HP1>(acc2, sU1, mbase, k16, sU2, k16, lane);

    // epilogue: dinv, bias, relu, scale, store fp16 g; pad adjacency
    int r1 = mbase + g, r2 = r1 + 8;
    int gm1 = m0 + r1, gm2 = m0 + r2;
    float dv1 = 0.f, dv2 = 0.f;
    int c1i = 0, c2i = 0;
    if (gm1 < nn) {
        c1i = d_cnt[gm1];
        dv1 = c1i > 0 ? rsqrtf((float)c1i) : 0.f;
        if (t == 0) d_dinv[gm1] = dv1;
    }
    if (gm2 < nn) {
        c2i = d_cnt[gm2];
        dv2 = c2i > 0 ? rsqrtf((float)c2i) : 0.f;
        if (t == 0) d_dinv[gm2] = dv2;
    }
    // pad adjacency to a multiple of 8 with dummy node NMAX (was pad_adj kernel)
    if (t == 1 && gm1 < nn) {
        int cc = min(c1i, SLOTS);
        int r = min((cc + 7) & ~7, SLOTS);
        for (int p = cc; p < r; p++) d_adj[(size_t)gm1 * SLOTS + p] = NMAX;
    }
    if (t == 2 && gm2 < nn) {
        int cc = min(c2i, SLOTS);
        int r = min((cc + 7) & ~7, SLOTS);
        for (int p = cc; p < r; p++) d_adj[(size_t)gm2 * SLOTS + p] = NMAX;
    }
#pragma unroll
    for (int nb = 0; nb < 8; nb++) {
        int n0 = nb * 8 + 2 * t;
        float bx = sB[64 + n0], by = sB[64 + n0 + 1];
        if (gm1 < nn) {
            float v0 = fmaxf(acc2[nb][0] + bx, 0.f) * dv1;
            float v1 = fmaxf(acc2[nb][1] + by, 0.f) * dv1;
            d_gh[(size_t)gm1 * 32 + (n0 >> 1)] = __floats2half2_rn(v0, v1);
        }
        if (gm2 < nn) {
            float v0 = fmaxf(acc2[nb][2] + bx, 0.f) * dv2;
            float v1 = fmaxf(acc2[nb][3] + by, 0.f) * dv2;
            d_gh[(size_t)gm2 * 32 + (n0 >> 1)] = __floats2half2_rn(v0, v1);
        }
    }
}

// ==================================================================
// gemm_tc (TENSOR-CORE, K=64): out = f((dinv*S) @ W + b)
// ==================================================================
template<int OUT_DST, bool RELU, bool SCALE_OUT>
__global__ __launch_bounds__(256, 2)
void gemm_tc(float* __restrict__ ext_out,
             const float* __restrict__ W, const float* __restrict__ bias, int nn) {
    __shared__ __align__(16) __half sA[128 * HP1];
    __shared__ __align__(16) __half sW[64 * HP1];
    __shared__ float sB[64];

    int tid = threadIdx.x;
    int warp = tid >> 5, lane = tid & 31;
    int m0 = blockIdx.x * 128;
    int mbase = warp * 16;

#pragma unroll
    for (int l = 0; l < 8; l++) {
        int fi = tid + l * 256;
        int node = fi >> 4;
        int q = fi & 15;
        int gm = m0 + node;
        float4 v = make_float4(0.f, 0.f, 0.f, 0.f);
        float dv = 0.f;
        if (gm < nn) {
            dv = d_dinv[gm];
            v = *(const float4*)&d_S[(size_t)gm * 64 + 4 * q];
        }
        __half2 h0 = __floats2half2_rn(v.x * dv, v.y * dv);
        __half2 h1 = __floats2half2_rn(v.z * dv, v.w * dv);
        uint2 pk; pk.x = *(unsigned*)&h0; pk.y = *(unsigned*)&h1;
        *(uint2*)&sA[node * HP1 + 4 * q] = pk;
    }
#pragma unroll
    for (int l = 0; l < 4; l++) {
        int fi = tid + l * 256;
        int k = fi >> 4;
        int n4 = (fi & 15) * 4;
        float4 w4 = __ldg((const float4*)(W + (size_t)k * 64 + n4));
        __half2 h0 = __floats2half2_rn(w4.x, w4.y);
        __half2 h1 = __floats2half2_rn(w4.z, w4.w);
        uint2 pk; pk.x = *(unsigned*)&h0; pk.y = *(unsigned*)&h1;
        *(uint2*)&sW[k * HP1 + n4] = pk;
    }
    if (tid < 64) sB[tid] = __ldg(bias + tid);
    __syncthreads();

    float acc[8][4];
#pragma unroll
    for (int i = 0; i < 8; i++)
#pragma unroll
        for (int j = 0; j < 4; j++) acc[i][j] = 0.f;
#pragma unroll
    for (int k16 = 0; k16 < 64; k16 += 16)
        mma_k16<HP1, HP1>(acc, sA, mbase, k16, sW, k16, lane);

    int g = lane >> 2, t = lane & 3;
    int r1 = mbase + g, r2 = r1 + 8;
    int gm1 = m0 + r1, gm2 = m0 + r2;
    float dv1 = 1.f, dv2 = 1.f;
    if (SCALE_OUT) {
        if (gm1 < nn) dv1 = d_dinv[gm1];
        if (gm2 < nn) dv2 = d_dinv[gm2];
    }
#pragma unroll
    for (int nb = 0; nb < 8; nb++) {
        int n0 = nb * 8 + 2 * t;
        float bx = sB[n0], by = sB[n0 + 1];
        if (gm1 < nn) {
            float v0 = acc[nb][0] + bx, v1 = acc[nb][1] + by;
            if (RELU) { v0 = fmaxf(v0, 0.f); v1 = fmaxf(v1, 0.f); }
            if (SCALE_OUT) { v0 *= dv1; v1 *= dv1; }
            if (OUT_DST == BUF_S)
                d_gh[(size_t)gm1 * 32 + (n0 >> 1)] = __floats2half2_rn(v0, v1);
            else
                *(float2*)&ext_out[(size_t)gm1 * 64 + n0] = make_float2(v0, v1);
        }
        if (gm2 < nn) {
            float v0 = acc[nb][2] + bx, v1 = acc[nb][3] + by;
            if (RELU) { v0 = fmaxf(v0, 0.f); v1 = fmaxf(v1, 0.f); }
            if (SCALE_OUT) { v0 *= dv2; v1 *= dv2; }
            if (OUT_DST == BUF_S)
                d_gh[(size_t)gm2 * 32 + (n0 >> 1)] = __floats2half2_rn(v0, v1);
            else
                *(float2*)&ext_out[(size_t)gm2 * 64 + n0] = make_float2(v0, v1);
        }
    }
}

// ------------------------------------------------------------------
// launch: 0 zero  1 fill  2 gemmA(profiled lands at idx3 w/ pad removed? keep order)
//         2 gemmA  3 gather1  4 gemmB  5 gather2  6 gemmC
// ------------------------------------------------------------------
extern "C" void kernel_launch(void* const* d_in, const int* in_sizes, int n_in,
                              void* d_out, int out_size) {
    const float* x     = (const float*)d_in[0];
    const int*   ei    = (const int*)d_in[1];     // int32 edge indices
    const float* W_in  = (const float*)d_in[2];
    const float* b_in  = (const float*)d_in[3];
    const float* W1    = (const float*)d_in[4];
    const float* b1    = (const float*)d_in[5];
    const float* W2    = (const float*)d_in[6];
    const float* b2    = (const float*)d_in[7];
    const float* W_out = (const float*)d_in[8];
    const float* b_out = (const float*)d_in[9];
    float* out = (float*)d_out;

    int N = in_sizes[0] / 128;   // 100000
    int E = in_sizes[1] / 2;     // 1600000
    const int* e0 = ei;
    const int* e1 = ei + E;

    int tileBlocks = (N + 127) / 128;
    int gatherBlocks = (N + 7) / 8;

    zero_cnt_kernel<<<(N + 255) / 256, 256>>>(N);
    fill_adj_kernel<<<(E + 255) / 256, 256>>>(e0, e1, E);

    // fused tensor-core: h, g, dinv, adjacency padding
    gemm_fused_A<<<tileBlocks, 256>>>(x, W_in, b_in, W1, b1, N);

    // propagate 1 (double-buffered gather; profiled slot idx 3)
    gather_kernel<<<gatherBlocks, 256>>>(N);

    // g = dinv * relu((dinv*S)@W2 + b2) -> d_gh (fp16)  [tensor core]
    gemm_tc<BUF_S, true, true><<<tileBlocks, 256>>>(nullptr, W2, b2, N);

    // propagate 2
    gather_kernel<<<gatherBlocks, 256>>>(N);

    // out = (dinv*S) @ W_out + b_out  (fp32 out)  [tensor core]
    gemm_tc<BUF_EXT, false, false><<<tileBlocks, 256>>>(out, W_out, b_out, N);
}